// round 15
// baseline (speedup 1.0000x reference)
#include <cuda_runtime.h>
#include <cuda_fp16.h>
#include <cstdint>

#define BB 32
#define LL 2048
#define DD 64
#define NKT 16            // 2048 / 128

// merged-kernel smem byte offsets (total 58880 -> 3 CTAs/SM)
#define QS_OFF   0          // half[128][72] = 18432
#define KS_OFF   18432      // half[128][72] = 18432 (phase1 k buf0, phase2 k)
#define VS_OFF   36864      // half[128][72] = 18432 (phase1 k buf1, phase2 v)
#define BMT_OFF  55296      // uint32[128][4] = 2048 (current tile only)
#define PART_OFF 57344      // float[256] = 1024
#define RINV_OFF 58368      // float[128] = 512
#define SMEM_TOTAL 58880

__device__ __half   g_qh[(size_t)BB * LL * DD];
__device__ __half   g_kh[(size_t)BB * LL * DD];
__device__ __half   g_vh[(size_t)BB * LL * DD];
__device__ uint32_t g_bm[(size_t)BB * LL * (LL / 32)];   // 16.8 MB bitmask

// ---------------- helpers ----------------
__device__ __forceinline__ uint32_t smem_u32(const void* p) {
    uint32_t a;
    asm("{ .reg .u64 t; cvta.to.shared.u64 t, %1; cvt.u32.u64 %0, t; }" : "=r"(a) : "l"(p));
    return a;
}
__device__ __forceinline__ void ldsm_x4(uint32_t addr, uint32_t* r) {
    asm volatile("ldmatrix.sync.aligned.m8n8.x4.shared.b16 {%0,%1,%2,%3}, [%4];"
                 : "=r"(r[0]), "=r"(r[1]), "=r"(r[2]), "=r"(r[3]) : "r"(addr));
}
__device__ __forceinline__ void ldsm_x4t(uint32_t addr, uint32_t* r) {
    asm volatile("ldmatrix.sync.aligned.m8n8.x4.trans.shared.b16 {%0,%1,%2,%3}, [%4];"
                 : "=r"(r[0]), "=r"(r[1]), "=r"(r[2]), "=r"(r[3]) : "r"(addr));
}
__device__ __forceinline__ void mma_f16(float* c, const uint32_t* a, const uint32_t* b) {
    asm volatile(
        "mma.sync.aligned.m16n8k16.row.col.f32.f16.f16.f32 "
        "{%0,%1,%2,%3}, {%4,%5,%6,%7}, {%8,%9}, {%0,%1,%2,%3};"
        : "+f"(c[0]), "+f"(c[1]), "+f"(c[2]), "+f"(c[3])
        : "r"(a[0]), "r"(a[1]), "r"(a[2]), "r"(a[3]), "r"(b[0]), "r"(b[1]));
}
__device__ __forceinline__ void cp16(uint32_t saddr, const void* g) {
    asm volatile("cp.async.cg.shared.global [%0], [%1], 16;" :: "r"(saddr), "l"(g));
}
__device__ __forceinline__ uint32_t h2pack(float a, float b) {
    __half2 h = __floats2half2_rn(a, b);
    return *(uint32_t*)&h;
}

// ---------- Kernel 1: normalize q,k -> fp16; convert v -> fp16 ----------
__global__ __launch_bounds__(256) void norm_kernel(const float* __restrict__ q,
                                                   const float* __restrict__ k,
                                                   const float* __restrict__ v) {
    int t = threadIdx.x;
    int rowInBlk = t >> 4;
    int lane = t & 15;
    long long row = (long long)blockIdx.x * 16 + rowInBlk;
    const long long BL = (long long)BB * LL;

    const float* src;
    __half* dst;
    bool donorm = true;
    long long r2 = row;
    if (r2 < BL) { src = q; dst = g_qh; }
    else if (r2 < 2 * BL) { src = k; dst = g_kh; r2 -= BL; }
    else { src = v; dst = g_vh; r2 -= 2 * BL; donorm = false; }

    const float4 w = *(const float4*)(src + r2 * DD + lane * 4);
    float ss = w.x * w.x + w.y * w.y + w.z * w.z + w.w * w.w;
#pragma unroll
    for (int o = 8; o; o >>= 1) ss += __shfl_xor_sync(0xffffffffu, ss, o, 16);
    float inv = donorm ? (1.0f / fmaxf(sqrtf(ss), 1e-12f)) : 1.0f;
    uint2 u;
    u.x = h2pack(w.x * inv, w.y * inv);
    u.y = h2pack(w.z * inv, w.w * inv);
    *(uint2*)(dst + r2 * DD + lane * 4) = u;
}

// ---------- Merged kernel: phase1 rowsums+bitmask, phase2 attn+PV ----------
// grid (16, 32), 256 thr (8 warps), 3 CTAs/SM (reg-capped).
__global__ __launch_bounds__(256, 3) void merged_kernel(const int* __restrict__ mask,
                                                        float* __restrict__ attn,
                                                        float* __restrict__ out) {
    extern __shared__ char smem[];
    uint32_t* bmt  = (uint32_t*)(smem + BMT_OFF);   // [128][4], current tile
    float*    part = (float*)(smem + PART_OFF);
    float*    rinv = (float*)(smem + RINV_OFF);
    const uint32_t smb = smem_u32(smem);

    const int b  = blockIdx.y;
    const int q0 = blockIdx.x * 128;
    const int t  = threadIdx.x;
    const int w  = t >> 5, lane = t & 31;
    const int g  = lane >> 2, c = lane & 3;

    const __half* kn = g_kh + (size_t)b * LL * DD;
    const __half* vn = g_vh + (size_t)b * LL * DD;

    // stage q tile [128][64]
    {
        int r = t >> 1, sg = (t & 1) * 32;
        const __half* qp = g_qh + ((size_t)b * LL + q0 + r) * DD + sg;
#pragma unroll
        for (int i = 0; i < 4; i++)
            *(uint4*)((__half*)(smem + QS_OFF) + r * 72 + sg + i * 8) =
                *(const uint4*)(qp + i * 8);
    }
    // prologue: cp.async k tile 0 -> buf0 (KS)
#pragma unroll
    for (int i = 0; i < 4; i++) {
        int idx = t + i * 256;
        int r = idx >> 3, seg = idx & 7;
        cp16(smb + KS_OFF + r * 144 + seg * 16, kn + (size_t)r * 64 + seg * 8);
    }
    asm volatile("cp.async.commit_group;");
    __syncthreads();   // q_s visible

    // ================= Phase 1: rowsums + bitmask =================
    {
        const int m0 = (w & 3) * 32, ni = w >> 2, n0 = ni * 64;
        const uint32_t aptr = smb + QS_OFF + (uint32_t)(m0 + (lane & 15)) * 144 + (lane >> 4) * 16;
        const uint32_t bptr = smb + KS_OFF +
            (uint32_t)(n0 + ((lane >> 4) << 3) + (lane & 7)) * 144 + ((lane >> 3) & 1) * 16;

        float rs[4] = {0.f, 0.f, 0.f, 0.f};
        uint32_t* bmrow = g_bm + ((size_t)b * LL + q0 + w * 16) * 64;

        for (int kt = 0; kt < NKT; kt++) {
            const int buf = kt & 1;
            __syncthreads();   // prev epilogue done with bmt; prev MMA done with buf
            // prefetch next k tile into other buffer
            if (kt + 1 < NKT) {
                const int nb = (kt + 1) & 1;
                const __half* kp = kn + (size_t)(kt + 1) * 128 * 64;
#pragma unroll
                for (int i = 0; i < 4; i++) {
                    int idx = t + i * 256;
                    int r = idx >> 3, seg = idx & 7;
                    cp16(smb + KS_OFF + nb * 18432 + r * 144 + seg * 16,
                         kp + (size_t)r * 64 + seg * 8);
                }
            }
            asm volatile("cp.async.commit_group;");

            // mask bitpack: warp w handles rows w*16..w*16+15; 1 LDG.128 + 3 shfl per row
            {
                const int* mbase = mask + ((size_t)b * LL + q0) * LL + (size_t)kt * 128;
#pragma unroll
                for (int i = 0; i < 16; i++) {
                    int row = w * 16 + i;
                    int4 m = __ldcs((const int4*)(mbase + (size_t)row * LL + lane * 4));
                    uint32_t nib = (uint32_t)(m.x != 0) | ((uint32_t)(m.y != 0) << 1) |
                                   ((uint32_t)(m.z != 0) << 2) | ((uint32_t)(m.w != 0) << 3);
                    uint32_t vv = nib << ((lane & 7) * 4);
                    vv |= __shfl_xor_sync(0xffffffffu, vv, 1);
                    vv |= __shfl_xor_sync(0xffffffffu, vv, 2);
                    vv |= __shfl_xor_sync(0xffffffffu, vv, 4);
                    if ((lane & 7) == 0) {
                        bmt[row * 4 + (lane >> 3)] = vv;
                        bmrow[(size_t)i * 64 + kt * 4 + (lane >> 3)] = vv;
                    }
                }
            }
            asm volatile("cp.async.wait_group 1;");
            __syncthreads();   // bmt tile + k_s(kt) visible

            // QK MMA + rowsums, in two N32 chunks (acc = 32 regs)
            const uint32_t bp = bptr + (uint32_t)buf * 18432;
#pragma unroll
            for (int ch = 0; ch < 2; ch++) {
                float acc[2][4][4];
#pragma unroll
                for (int mf = 0; mf < 2; mf++)
#pragma unroll
                    for (int nf = 0; nf < 4; nf++)
#pragma unroll
                        for (int e = 0; e < 4; e++) acc[mf][nf][e] = 0.f;

#pragma unroll
                for (int s = 0; s < 4; s++) {
                    uint32_t a0[4], a1[4];
                    ldsm_x4(aptr + s * 32, a0);
                    ldsm_x4(aptr + 16 * 144 + s * 32, a1);
#pragma unroll
                    for (int nbp = 0; nbp < 2; nbp++) {
                        uint32_t bb[4];
                        ldsm_x4(bp + (uint32_t)(ch * 2 + nbp) * 16 * 144 + s * 32, bb);
                        mma_f16(acc[0][nbp * 2],     a0, bb);
                        mma_f16(acc[0][nbp * 2 + 1], a0, bb + 2);
                        mma_f16(acc[1][nbp * 2],     a1, bb);
                        mma_f16(acc[1][nbp * 2 + 1], a1, bb + 2);
                    }
                }

#pragma unroll
                for (int mf = 0; mf < 2; mf++) {
                    int r0 = m0 + mf * 16 + g;
#pragma unroll
                    for (int nf = 0; nf < 4; nf++) {
                        int col = n0 + ch * 32 + nf * 8 + 2 * c;
                        uint32_t wA = bmt[r0 * 4 + (col >> 5)];
                        uint32_t wB = bmt[(r0 + 8) * 4 + (col >> 5)];
                        int sh = col & 31;
                        float s0 = ((wA >> sh) & 1u)       ? 0.f : acc[mf][nf][0] + 1.f;
                        float s1 = ((wA >> (sh + 1)) & 1u) ? 0.f : acc[mf][nf][1] + 1.f;
                        float s2 = ((wB >> sh) & 1u)       ? 0.f : acc[mf][nf][2] + 1.f;
                        float s3 = ((wB >> (sh + 1)) & 1u) ? 0.f : acc[mf][nf][3] + 1.f;
                        rs[mf * 2 + 0] += s0 + s1;
                        rs[mf * 2 + 1] += s2 + s3;
                    }
                }
            }
        }

        // rowsums: reduce over c lanes, combine two ni halves via smem
#pragma unroll
        for (int i = 0; i < 4; i++) {
            float vs = rs[i];
            vs += __shfl_xor_sync(0xffffffffu, vs, 1);
            vs += __shfl_xor_sync(0xffffffffu, vs, 2);
            rs[i] = vs;
        }
        if (c == 0) {
            part[(m0 + g) * 2 + ni]      = rs[0];
            part[(m0 + g + 8) * 2 + ni]  = rs[1];
            part[(m0 + 16 + g) * 2 + ni] = rs[2];
            part[(m0 + 24 + g) * 2 + ni] = rs[3];
        }
        __syncthreads();
        if (t < 128) rinv[t] = 1.0f / fmaxf(part[t * 2] + part[t * 2 + 1], 1e-12f);
        __syncthreads();
    }

    // ================= Phase 2: QK recompute -> direct attn write + PV =================
    {
        const int r0 = w * 16;
        const uint32_t aptr = smb + QS_OFF + (uint32_t)(r0 + (lane & 15)) * 144 + (lane >> 4) * 16;
        const uint32_t bptr = smb + KS_OFF +
            (uint32_t)(((lane >> 4) << 3) + (lane & 7)) * 144 + ((lane >> 3) & 1) * 16;
        const uint32_t vptr = smb + VS_OFF + (uint32_t)(lane & 15) * 144 + (lane >> 4) * 16;

        // persistent q fragments (16 regs, zero A-LDSM in the loop)
        uint32_t aq[4][4];
#pragma unroll
        for (int s = 0; s < 4; s++) ldsm_x4(aptr + s * 32, aq[s]);

        float oacc[8][4];
#pragma unroll
        for (int nb = 0; nb < 8; nb++)
#pragma unroll
            for (int e = 0; e < 4; e++) oacc[nb][e] = 0.f;

        const float ri0 = rinv[r0 + g];
        const float ri1 = rinv[r0 + g + 8];
        float* arowA = attn + ((size_t)b * LL + q0 + r0 + g) * LL;
        float* arowB = arowA + (size_t)8 * LL;
        const uint32_t* bmrA = g_bm + ((size_t)b * LL + q0 + r0 + g) * 64;
        const uint32_t* bmrB = bmrA + (size_t)8 * 64;

        for (int kt = 0; kt < NKT; kt++) {
            __syncthreads();   // all warps done with k_s/v_s of prev tile
            {
                const __half* kp = kn + (size_t)kt * 128 * 64;
                const __half* vp = vn + (size_t)kt * 128 * 64;
#pragma unroll
                for (int i = 0; i < 4; i++) {
                    int idx = t + i * 256;
                    int r = idx >> 3, seg = idx & 7;
                    cp16(smb + KS_OFF + r * 144 + seg * 16, kp + (size_t)r * 64 + seg * 8);
                    cp16(smb + VS_OFF + r * 144 + seg * 16, vp + (size_t)r * 64 + seg * 8);
                }
            }
            asm volatile("cp.async.commit_group;");
            // bitmask for this thread's two rows (same-CTA producer -> L2-hot)
            uint32_t bmA[4], bmB[4];
            *(uint4*)bmA = *(const uint4*)(bmrA + kt * 4);
            *(uint4*)bmB = *(const uint4*)(bmrB + kt * 4);
            asm volatile("cp.async.wait_group 0;");
            __syncthreads();

            // four 32-col quarters: QK (acc 16 regs) -> epilogue -> PV
#pragma unroll
            for (int qd = 0; qd < 4; qd++) {
                float acc[4][4];
#pragma unroll
                for (int nf = 0; nf < 4; nf++)
#pragma unroll
                    for (int e = 0; e < 4; e++) acc[nf][e] = 0.f;

#pragma unroll
                for (int s = 0; s < 4; s++) {
#pragma unroll
                    for (int nbp = 0; nbp < 2; nbp++) {
                        uint32_t bb[4];
                        ldsm_x4(bptr + (uint32_t)(qd * 2 + nbp) * 2304 + s * 32, bb);
                        mma_f16(acc[nbp * 2],     aq[s], bb);
                        mma_f16(acc[nbp * 2 + 1], aq[s], bb + 2);
                    }
                }

#pragma unroll
                for (int ks = 0; ks < 2; ks++) {
                    uint32_t af[4];
#pragma unroll
                    for (int p = 0; p < 2; p++) {
                        int nf = 2 * ks + p;
                        int col = qd * 32 + nf * 8 + 2 * c;
                        uint32_t wA = bmA[col >> 5];
                        uint32_t wB = bmB[col >> 5];
                        int sh = col & 31;
                        float s0 = ((wA >> sh) & 1u)       ? 0.f : acc[nf][0] + 1.f;
                        float s1 = ((wA >> (sh + 1)) & 1u) ? 0.f : acc[nf][1] + 1.f;
                        float s2 = ((wB >> sh) & 1u)       ? 0.f : acc[nf][2] + 1.f;
                        float s3 = ((wB >> (sh + 1)) & 1u) ? 0.f : acc[nf][3] + 1.f;
                        af[p * 2]     = h2pack(s0, s1);
                        af[p * 2 + 1] = h2pack(s2, s3);
                        int gcol = kt * 128 + col;
                        __stcs((float2*)(arowA + gcol), make_float2(s0 * ri0, s1 * ri0));
                        __stcs((float2*)(arowB + gcol), make_float2(s2 * ri1, s3 * ri1));
                    }
                    int gks = qd * 2 + ks;
#pragma unroll
                    for (int db = 0; db < 4; db++) {
                        uint32_t bb[4];
                        ldsm_x4t(vptr + (uint32_t)gks * 2304 + db * 32, bb);
                        mma_f16(oacc[db * 2],     af, bb);
                        mma_f16(oacc[db * 2 + 1], af, bb + 2);
                    }
                }
            }
        }

        // O epilogue: scale rows by rinv, write
        float* o0 = out + ((size_t)b * LL + q0 + r0 + g) * DD;
        float* o1 = o0 + (size_t)8 * DD;
#pragma unroll
        for (int nb = 0; nb < 8; nb++) {
            int col = nb * 8 + 2 * c;
            *(float2*)(o0 + col) = make_float2(oacc[nb][0] * ri0, oacc[nb][1] * ri0);
            *(float2*)(o1 + col) = make_float2(oacc[nb][2] * ri1, oacc[nb][3] * ri1);
        }
    }
}

// ---------------- launch ----------------
extern "C" void kernel_launch(void* const* d_in, const int* in_sizes, int n_in,
                              void* d_out, int out_size) {
    const float* q = (const float*)d_in[0];
    const float* k = (const float*)d_in[1];
    const float* v = (const float*)d_in[2];
    const int* mask = (const int*)d_in[3];

    float* out = (float*)d_out;
    float* attn = out + (size_t)BB * LL * DD;

    cudaFuncSetAttribute(merged_kernel, cudaFuncAttributeMaxDynamicSharedMemorySize,
                         SMEM_TOTAL);

    norm_kernel<<<(3 * BB * LL) / 16, 256>>>(q, k, v);
    merged_kernel<<<dim3(LL / 128, BB), 256, SMEM_TOTAL>>>(mask, attn, out);
}

// round 16
// speedup vs baseline: 1.8212x; 1.8212x over previous
#include <cuda_runtime.h>
#include <cuda_fp16.h>
#include <cstdint>

#define BB 32
#define LL 2048
#define DD 64
#define NKT 16            // 2048 / 128

// strides in halfs
#define KSP 72            // q_s / k_s / v_s row stride (144 B)
#define SSP 136           // s_s row stride (272 B)

// pass1 smem (bytes)
#define P1_QS   0
#define P1_KS   18432     // 2 x half[128][72] = 2 x 18432
#define P1_BMT  55296     // uint32[512]
#define P1_PART 57344     // float[256]
#define P1_SMEM 58368

// pass2 smem (bytes)
#define P2_QS   0
#define P2_KS   18432
#define P2_VS   36864
#define P2_SS   55296     // half[128*136] = 34816
#define P2_RINV 90112     // float[128]
#define P2_SMEM 90624

__device__ __half   g_qh[(size_t)BB * LL * DD];
__device__ __half   g_kh[(size_t)BB * LL * DD];
__device__ __half   g_vh[(size_t)BB * LL * DD];
__device__ uint32_t g_bm[(size_t)BB * LL * (LL / 32)];   // 16.8 MB bitmask
__device__ float    g_rinv[(size_t)BB * LL];

// ---------------- helpers ----------------
__device__ __forceinline__ uint32_t smem_u32(const void* p) {
    uint32_t a;
    asm("{ .reg .u64 t; cvta.to.shared.u64 t, %1; cvt.u32.u64 %0, t; }" : "=r"(a) : "l"(p));
    return a;
}
__device__ __forceinline__ void ldsm_x4(uint32_t addr, uint32_t* r) {
    asm volatile("ldmatrix.sync.aligned.m8n8.x4.shared.b16 {%0,%1,%2,%3}, [%4];"
                 : "=r"(r[0]), "=r"(r[1]), "=r"(r[2]), "=r"(r[3]) : "r"(addr));
}
__device__ __forceinline__ void ldsm_x4t(uint32_t addr, uint32_t* r) {
    asm volatile("ldmatrix.sync.aligned.m8n8.x4.trans.shared.b16 {%0,%1,%2,%3}, [%4];"
                 : "=r"(r[0]), "=r"(r[1]), "=r"(r[2]), "=r"(r[3]) : "r"(addr));
}
__device__ __forceinline__ void mma_f16(float* c, const uint32_t* a, const uint32_t* b) {
    asm volatile(
        "mma.sync.aligned.m16n8k16.row.col.f32.f16.f16.f32 "
        "{%0,%1,%2,%3}, {%4,%5,%6,%7}, {%8,%9}, {%0,%1,%2,%3};"
        : "+f"(c[0]), "+f"(c[1]), "+f"(c[2]), "+f"(c[3])
        : "r"(a[0]), "r"(a[1]), "r"(a[2]), "r"(a[3]), "r"(b[0]), "r"(b[1]));
}
__device__ __forceinline__ void cp16(uint32_t saddr, const void* g) {
    asm volatile("cp.async.cg.shared.global [%0], [%1], 16;" :: "r"(saddr), "l"(g));
}
__device__ __forceinline__ uint32_t h2pack(float a, float b) {
    __half2 h = __floats2half2_rn(a, b);
    return *(uint32_t*)&h;
}

// ---------- Kernel 1: normalize q,k -> fp16; convert v -> fp16 ----------
__global__ __launch_bounds__(256) void norm_kernel(const float* __restrict__ q,
                                                   const float* __restrict__ k,
                                                   const float* __restrict__ v) {
    int t = threadIdx.x;
    int rowInBlk = t >> 4;
    int lane = t & 15;
    long long row = (long long)blockIdx.x * 16 + rowInBlk;
    const long long BL = (long long)BB * LL;

    const float* src;
    __half* dst;
    bool donorm = true;
    long long r2 = row;
    if (r2 < BL) { src = q; dst = g_qh; }
    else if (r2 < 2 * BL) { src = k; dst = g_kh; r2 -= BL; }
    else { src = v; dst = g_vh; r2 -= 2 * BL; donorm = false; }

    const float4 w = *(const float4*)(src + r2 * DD + lane * 4);
    float ss = w.x * w.x + w.y * w.y + w.z * w.z + w.w * w.w;
#pragma unroll
    for (int o = 8; o; o >>= 1) ss += __shfl_xor_sync(0xffffffffu, ss, o, 16);
    float inv = donorm ? (1.0f / fmaxf(sqrtf(ss), 1e-12f)) : 1.0f;
    uint2 u;
    u.x = h2pack(w.x * inv, w.y * inv);
    u.y = h2pack(w.z * inv, w.w * inv);
    *(uint2*)(dst + r2 * DD + lane * 4) = u;
}

// ---------- Pass 1: QK rowsums + mask bitpack (cp.async double-buffered) ----------
// grid (16, 32), 256 thr. warp w: m0=(w&3)*32 (32q), n0=(w>>2)*64 (64k).
__global__ __launch_bounds__(256, 2) void pass1_kernel(const int* __restrict__ mask) {
    extern __shared__ char smem[];
    __half*   q_s  = (__half*)(smem + P1_QS);
    uint32_t* bmt  = (uint32_t*)(smem + P1_BMT);
    float*    part = (float*)(smem + P1_PART);
    const uint32_t smb = smem_u32(smem);

    const int b = blockIdx.y;
    const int q0 = blockIdx.x * 128;
    const int t = threadIdx.x;
    const int w = t >> 5, lane = t & 31;
    const int g = lane >> 2, c = lane & 3;
    const int m0 = (w & 3) * 32, ni = w >> 2, n0 = ni * 64;

    const __half* kn = g_kh + (size_t)b * LL * DD;

    // stage q tile [128][64] fp16
    {
        int r = t >> 1, sg = (t & 1) * 32;
        const __half* qp = g_qh + ((size_t)b * LL + q0 + r) * DD + sg;
#pragma unroll
        for (int i = 0; i < 4; i++)
            *(uint4*)&q_s[r * KSP + sg + i * 8] = *(const uint4*)(qp + i * 8);
    }
    // prologue: cp.async k tile 0 -> buf0
#pragma unroll
    for (int i = 0; i < 4; i++) {
        int idx = t + i * 256;
        int r = idx >> 3, seg = idx & 7;
        cp16(smb + P1_KS + r * 144 + seg * 16, kn + (size_t)r * 64 + seg * 8);
    }
    asm volatile("cp.async.commit_group;");
    __syncthreads();   // q_s visible

    const uint32_t aptr = smb + P1_QS + (uint32_t)(m0 + (lane & 15)) * 144 + (lane >> 4) * 16;
    const uint32_t bptr = smb + P1_KS +
        (uint32_t)(n0 + ((lane >> 4) << 3) + (lane & 7)) * 144 + ((lane >> 3) & 1) * 16;

    float rs[4] = {0.f, 0.f, 0.f, 0.f};

    for (int kt = 0; kt < NKT; kt++) {
        const int buf = kt & 1;
        __syncthreads();   // prev epilogue done with bmt; prev MMA done with the buf being refilled

        // prefetch next k tile into other buffer
        if (kt + 1 < NKT) {
            const int nb = (kt + 1) & 1;
            const __half* kp = kn + (size_t)(kt + 1) * 128 * 64;
#pragma unroll
            for (int i = 0; i < 4; i++) {
                int idx = t + i * 256;
                int r = idx >> 3, seg = idx & 7;
                cp16(smb + P1_KS + nb * 18432 + r * 144 + seg * 16,
                     kp + (size_t)r * 64 + seg * 8);
            }
        }
        asm volatile("cp.async.commit_group;");

        // mask bitpack: warp w handles rows w*16..w*16+15; 1 LDG.128 + 3 shfl per row
        {
            const int* mbase = mask + ((size_t)b * LL + q0) * LL + (size_t)kt * 128;
#pragma unroll
            for (int i = 0; i < 16; i++) {
                int row = w * 16 + i;
                int4 m = __ldcs((const int4*)(mbase + (size_t)row * LL + lane * 4));
                uint32_t nib = (uint32_t)(m.x != 0) | ((uint32_t)(m.y != 0) << 1) |
                               ((uint32_t)(m.z != 0) << 2) | ((uint32_t)(m.w != 0) << 3);
                uint32_t vv = nib << ((lane & 7) * 4);
                vv |= __shfl_xor_sync(0xffffffffu, vv, 1);
                vv |= __shfl_xor_sync(0xffffffffu, vv, 2);
                vv |= __shfl_xor_sync(0xffffffffu, vv, 4);
                if ((lane & 7) == 0)
                    bmt[row * 4 + (lane >> 3)] = vv;
            }
        }
        asm volatile("cp.async.wait_group 1;");
        __syncthreads();   // bmt tile + k_s(kt) visible

        // persist bitmask tile (read back by pass2; L2-hot)
        if (t < 128)
            *(uint4*)&g_bm[((size_t)b * LL + q0 + t) * 64 + kt * 4] =
                *(const uint4*)&bmt[t * 4];

        // QK MMA: warp = M32 x N64
        float acc[2][8][4];
#pragma unroll
        for (int mf = 0; mf < 2; mf++)
#pragma unroll
            for (int nf = 0; nf < 8; nf++)
#pragma unroll
                for (int e = 0; e < 4; e++) acc[mf][nf][e] = 0.f;

        const uint32_t bp = bptr + (uint32_t)buf * 18432;
#pragma unroll
        for (int s = 0; s < 4; s++) {
            uint32_t a0[4], a1[4];
            ldsm_x4(aptr + s * 32, a0);
            ldsm_x4(aptr + 16 * 144 + s * 32, a1);
#pragma unroll
            for (int nfp = 0; nfp < 4; nfp++) {
                uint32_t bb[4];
                ldsm_x4(bp + (uint32_t)nfp * 16 * 144 + s * 32, bb);
                mma_f16(acc[0][nfp * 2],     a0, bb);
                mma_f16(acc[0][nfp * 2 + 1], a0, bb + 2);
                mma_f16(acc[1][nfp * 2],     a1, bb);
                mma_f16(acc[1][nfp * 2 + 1], a1, bb + 2);
            }
        }

        // rowsum epilogue (bits from smem)
#pragma unroll
        for (int mf = 0; mf < 2; mf++) {
            int r0 = m0 + mf * 16 + g;
#pragma unroll
            for (int nf = 0; nf < 8; nf++) {
                int col = n0 + nf * 8 + 2 * c;
                uint32_t wA = bmt[r0 * 4 + (col >> 5)];
                uint32_t wB = bmt[(r0 + 8) * 4 + (col >> 5)];
                int sh = col & 31;
                float s0 = ((wA >> sh) & 1u)       ? 0.f : acc[mf][nf][0] + 1.f;
                float s1 = ((wA >> (sh + 1)) & 1u) ? 0.f : acc[mf][nf][1] + 1.f;
                float s2 = ((wB >> sh) & 1u)       ? 0.f : acc[mf][nf][2] + 1.f;
                float s3 = ((wB >> (sh + 1)) & 1u) ? 0.f : acc[mf][nf][3] + 1.f;
                rs[mf * 2 + 0] += s0 + s1;
                rs[mf * 2 + 1] += s2 + s3;
            }
        }
    }

    // rowsums: reduce over c lanes, combine two ni halves via smem
#pragma unroll
    for (int i = 0; i < 4; i++) {
        float vs = rs[i];
        vs += __shfl_xor_sync(0xffffffffu, vs, 1);
        vs += __shfl_xor_sync(0xffffffffu, vs, 2);
        rs[i] = vs;
    }
    if (c == 0) {
        part[(m0 + g) * 2 + ni]      = rs[0];
        part[(m0 + g + 8) * 2 + ni]  = rs[1];
        part[(m0 + 16 + g) * 2 + ni] = rs[2];
        part[(m0 + 24 + g) * 2 + ni] = rs[3];
    }
    __syncthreads();
    if (t < 128)
        g_rinv[(size_t)b * LL + q0 + t] =
            1.0f / fmaxf(part[t * 2] + part[t * 2 + 1], 1e-12f);
}

// ---------- Pass 2: QK recompute -> attn write + PV (reg-resident A) ----------
// grid (16, 32), 256 thr. warp w owns q rows w*16..w*16+15, full 128 k per tile.
__global__ __launch_bounds__(256, 2) void pass2_kernel(float* __restrict__ attn,
                                                       float* __restrict__ out) {
    extern __shared__ char smem[];
    __half* q_s  = (__half*)(smem + P2_QS);
    __half* s_s  = (__half*)(smem + P2_SS);
    float*  rinv = (float*)(smem + P2_RINV);
    const uint32_t smb = smem_u32(smem);

    const int b = blockIdx.y;
    const int q0 = blockIdx.x * 128;
    const int t = threadIdx.x;
    const int w = t >> 5, lane = t & 31;
    const int g = lane >> 2, c = lane & 3;
    const int r0 = w * 16;

    if (t < 128) rinv[t] = g_rinv[(size_t)b * LL + q0 + t];

    // stage q tile
    {
        int r = t >> 1, sg = (t & 1) * 32;
        const __half* qp = g_qh + ((size_t)b * LL + q0 + r) * DD + sg;
#pragma unroll
        for (int i = 0; i < 4; i++)
            *(uint4*)&q_s[r * KSP + sg + i * 8] = *(const uint4*)(qp + i * 8);
    }

    const uint32_t aptr = smb + P2_QS + (uint32_t)(r0 + (lane & 15)) * 144 + (lane >> 4) * 16;
    const uint32_t bptr = smb + P2_KS +
        (uint32_t)(((lane >> 4) << 3) + (lane & 7)) * 144 + ((lane >> 3) & 1) * 16;
    const uint32_t vptr = smb + P2_VS + (uint32_t)(lane & 15) * 144 + (lane >> 4) * 16;

    float oacc[8][4];
#pragma unroll
    for (int nb = 0; nb < 8; nb++)
#pragma unroll
        for (int e = 0; e < 4; e++) oacc[nb][e] = 0.f;

    const __half* kn = g_kh + (size_t)b * LL * DD;
    const __half* vn = g_vh + (size_t)b * LL * DD;
    const uint32_t* bmrA = g_bm + ((size_t)b * LL + q0 + r0 + g) * 64;
    const uint32_t* bmrB = bmrA + (size_t)8 * 64;

    for (int kt = 0; kt < NKT; kt++) {
        __syncthreads();   // all warps done with k_s/v_s of prev tile
        // cp.async stage k,v tiles [128][64] fp16
        {
            const __half* kbase = kn + (size_t)kt * 128 * DD;
            const __half* vbase = vn + (size_t)kt * 128 * DD;
#pragma unroll
            for (int i = 0; i < 4; i++) {
                int idx = t + i * 256;
                int r = idx >> 3, seg = idx & 7;
                cp16(smb + P2_KS + r * 144 + seg * 16, kbase + r * 64 + seg * 8);
                cp16(smb + P2_VS + r * 144 + seg * 16, vbase + r * 64 + seg * 8);
            }
        }
        asm volatile("cp.async.commit_group;");
        // bitmask for this thread's two rows (L2-hot)
        uint4 bA = *(const uint4*)(bmrA + kt * 4);
        uint4 bB = *(const uint4*)(bmrB + kt * 4);
        uint32_t bmA[4] = {bA.x, bA.y, bA.z, bA.w};
        uint32_t bmB[4] = {bB.x, bB.y, bB.z, bB.w};
        asm volatile("cp.async.wait_group 0;");
        __syncthreads();

        // two 64-col halves: QK -> epilogue -> PV (A from registers)
#pragma unroll
        for (int h = 0; h < 2; h++) {
            float acc[8][4];
#pragma unroll
            for (int nf = 0; nf < 8; nf++)
#pragma unroll
                for (int e = 0; e < 4; e++) acc[nf][e] = 0.f;

#pragma unroll
            for (int s = 0; s < 4; s++) {
                uint32_t a[4];
                ldsm_x4(aptr + s * 32, a);
#pragma unroll
                for (int nb = 0; nb < 4; nb++) {
                    uint32_t bb[4];
                    ldsm_x4(bptr + (uint32_t)(h * 4 + nb) * 2304 + s * 32, bb);
                    mma_f16(acc[nb * 2],     a, bb);
                    mma_f16(acc[nb * 2 + 1], a, bb + 2);
                }
            }

#pragma unroll
            for (int ks = 0; ks < 4; ks++) {
                uint32_t af[4];
#pragma unroll
                for (int p = 0; p < 2; p++) {
                    int nf = 2 * ks + p;
                    int col = h * 64 + nf * 8 + 2 * c;
                    uint32_t wA = bmA[col >> 5];
                    uint32_t wB = bmB[col >> 5];
                    int sh = col & 31;
                    float s0 = ((wA >> sh) & 1u)       ? 0.f : acc[nf][0] + 1.f;
                    float s1 = ((wA >> (sh + 1)) & 1u) ? 0.f : acc[nf][1] + 1.f;
                    float s2 = ((wB >> sh) & 1u)       ? 0.f : acc[nf][2] + 1.f;
                    float s3 = ((wB >> (sh + 1)) & 1u) ? 0.f : acc[nf][3] + 1.f;
                    uint32_t hA = h2pack(s0, s1);
                    uint32_t hB = h2pack(s2, s3);
                    af[p * 2]     = hA;
                    af[p * 2 + 1] = hB;
                    *(uint32_t*)&s_s[(r0 + g) * SSP + col]     = hA;
                    *(uint32_t*)&s_s[(r0 + g + 8) * SSP + col] = hB;
                }
                int gks = h * 4 + ks;
#pragma unroll
                for (int db = 0; db < 4; db++) {
                    uint32_t bb[4];
                    ldsm_x4t(vptr + (uint32_t)gks * 2304 + db * 32, bb);
                    mma_f16(oacc[db * 2],     af, bb);
                    mma_f16(oacc[db * 2 + 1], af, bb + 2);
                }
            }
        }

        __syncwarp();   // s_s rows complete within warp
        // attn write (normalized fp32), warp-private rows, coalesced
#pragma unroll
        for (int i = 0; i < 16; i++) {
            int row = r0 + i;
            uint2 raw = *(const uint2*)&s_s[row * SSP + lane * 4];
            float ri = rinv[row];
            float2 f0 = __half22float2(*(__half2*)&raw.x);
            float2 f1 = __half22float2(*(__half2*)&raw.y);
            float4 o = make_float4(f0.x * ri, f0.y * ri, f1.x * ri, f1.y * ri);
            __stcs((float4*)(attn + ((size_t)b * LL + q0 + row) * LL +
                             (size_t)kt * 128 + lane * 4), o);
        }
        __syncwarp();
    }

    // O epilogue: scale rows by rinv, write
    float riA = rinv[r0 + g], riB = rinv[r0 + g + 8];
    float* o0 = out + ((size_t)b * LL + q0 + r0 + g) * DD;
    float* o1 = o0 + (size_t)8 * DD;
#pragma unroll
    for (int nb = 0; nb < 8; nb++) {
        int col = nb * 8 + 2 * c;
        *(float2*)(o0 + col) = make_float2(oacc[nb][0] * riA, oacc[nb][1] * riA);
        *(float2*)(o1 + col) = make_float2(oacc[nb][2] * riB, oacc[nb][3] * riB);
    }
}

// ---------------- launch ----------------
extern "C" void kernel_launch(void* const* d_in, const int* in_sizes, int n_in,
                              void* d_out, int out_size) {
    const float* q = (const float*)d_in[0];
    const float* k = (const float*)d_in[1];
    const float* v = (const float*)d_in[2];
    const int* mask = (const int*)d_in[3];

    float* out = (float*)d_out;
    float* attn = out + (size_t)BB * LL * DD;

    cudaFuncSetAttribute(pass1_kernel, cudaFuncAttributeMaxDynamicSharedMemorySize, P1_SMEM);
    cudaFuncSetAttribute(pass2_kernel, cudaFuncAttributeMaxDynamicSharedMemorySize, P2_SMEM);

    norm_kernel<<<(3 * BB * LL) / 16, 256>>>(q, k, v);
    pass1_kernel<<<dim3(LL / 128, BB), 256, P1_SMEM>>>(mask);
    pass2_kernel<<<dim3(LL / 128, BB), 256, P2_SMEM>>>(attn, out);
}